// round 6
// baseline (speedup 1.0000x reference)
#include <cuda_runtime.h>
#include <cuda_bf16.h>
#include <math.h>
#include <stdint.h>

#define D_DIM 128
#define K_DIM 512
#define TMROWS 64
#define NTHREADS 256
#define SOFTMIN_BETA 10.0f

#define DSTRIDE 516                       // s_dist row stride (floats)
#define RSTRIDE 272                       // staged row stride (bytes): 256B data + 16 pad
#define ASZ (64 * RSTRIDE)                // 17408 bytes per A split
#define BSZ (64 * RSTRIDE)                // 17408 bytes per B split chunk (64 rows)
#define OFF_A (TMROWS * DSTRIDE * 4)      // 132096
#define OFF_B (OFF_A + 2 * ASZ)           // 166912
#define OFF_TAIL (OFF_B + 2 * BSZ)        // 201728
#define SMEM_BYTES (OFF_TAIL + 2560)      // 204288

// ---------------- device globals (allocation-free scratch) ----------------
__device__ double g_sq_sum;
__device__ double g_mind_sum;
__device__ unsigned int g_counts[K_DIM];
__device__ float g_emb_sq[K_DIM];
__device__ __align__(16) __nv_bfloat16 g_bsplit[2][K_DIM * D_DIM];   // [split][n][d]

// ---------------- PTX helpers (baseline PTX only: sm_103 target) ----------------
__device__ __forceinline__ uint32_t smem_to_u32(const void* p) {
    uint32_t a;
    asm("{ .reg .u64 t; cvta.to.shared.u64 t, %1; cvt.u32.u64 %0, t; }" : "=r"(a) : "l"(p));
    return a;
}
#define LDSM_X4(r0, r1, r2, r3, addr) \
    asm volatile("ldmatrix.sync.aligned.m8n8.x4.shared.b16 {%0,%1,%2,%3}, [%4];" \
                 : "=r"(r0), "=r"(r1), "=r"(r2), "=r"(r3) : "r"(addr))

__device__ __forceinline__ void mma16816(float* c, const uint32_t* a, uint32_t b0, uint32_t b1) {
    asm volatile(
        "mma.sync.aligned.m16n8k16.row.col.f32.bf16.bf16.f32 "
        "{%0,%1,%2,%3}, {%4,%5,%6,%7}, {%8,%9}, {%0,%1,%2,%3};"
        : "+f"(c[0]), "+f"(c[1]), "+f"(c[2]), "+f"(c[3])
        : "r"(a[0]), "r"(a[1]), "r"(a[2]), "r"(a[3]), "r"(b0), "r"(b1));
}

// ---------------- init: zeros, embsq (exact ref order), emb bf16 2-splits ----------------
__global__ void vq_init_kernel(const float* __restrict__ emb) {
    int k = blockIdx.x * 32 + threadIdx.x;   // grid 16 x 32 = 512
    if (k == 0) { g_sq_sum = 0.0; g_mind_sum = 0.0; }
    g_counts[k] = 0u;
    const float* e = emb + (size_t)k * D_DIM;
    float s = 0.f;
    for (int d = 0; d < D_DIM; ++d) {
        float x = e[d];
        s = __fadd_rn(s, __fmul_rn(x, x));
        __nv_bfloat16 b0 = __float2bfloat16(x);
        __nv_bfloat16 b1 = __float2bfloat16(x - __bfloat162float(b0));
        g_bsplit[0][k * D_DIM + d] = b0;
        g_bsplit[1][k * D_DIM + d] = b1;
    }
    g_emb_sq[k] = s;
}

// ---------------- main kernel ----------------
__global__ void __launch_bounds__(NTHREADS) vq_main_kernel(
    const float* __restrict__ latents,
    const float* __restrict__ emb,
    float* __restrict__ out_q,
    float* __restrict__ out_ind,
    float* __restrict__ out_soft)
{
    extern __shared__ __align__(16) unsigned char smem[];
    float* s_dist = (float*)smem;                       // 64 x DSTRIDE
    unsigned char* s_a = smem + OFF_A;                  // 2 splits x 64 rows x RSTRIDE
    unsigned char* s_b = smem + OFF_B;                  // 2 splits x 64 rows x RSTRIDE
    float* s_rowsq = (float*)(smem + OFF_TAIL);         // 64
    float* s_esq   = s_rowsq + 64;                      // 512

    const int tid = threadIdx.x;
    const int wid = tid >> 5, lane = tid & 31;
    const long long row0 = (long long)blockIdx.x * TMROWS;
    const uint32_t sbase = smem_to_u32(smem);

    // esq copy
    s_esq[tid] = g_emb_sq[tid];
    s_esq[256 + tid] = g_emb_sq[256 + tid];

    // A staging: bf16 2-split of latent tile into 272B-stride rows
    {
        const float2* g = (const float2*)(latents + row0 * D_DIM);
#pragma unroll
        for (int it = 0; it < 16; ++it) {
            int u = it * NTHREADS + tid;     // 64 rows x 64 pairs
            int row = u >> 6, dp = u & 63;
            float2 x = g[u];
            __nv_bfloat162 lo, hi;
            lo.x = __float2bfloat16(x.x);
            hi.x = __float2bfloat16(x.x - __bfloat162float(lo.x));
            lo.y = __float2bfloat16(x.y);
            hi.y = __float2bfloat16(x.y - __bfloat162float(lo.y));
            *(__nv_bfloat162*)(s_a + 0 * ASZ + row * RSTRIDE + dp * 4) = lo;
            *(__nv_bfloat162*)(s_a + 1 * ASZ + row * RSTRIDE + dp * 4) = hi;
        }
    }
    // rowsq: exact reference-order chain
    if (tid < TMROWS) {
        const float* lr = latents + (row0 + tid) * D_DIM;
        float s = 0.f;
        for (int d = 0; d < D_DIM; ++d)
            s = __fadd_rn(s, __fmul_rn(lr[d], lr[d]));
        s_rowsq[tid] = s;
    }

    // B chunk staging mapping (register double-buffer)
    const float4* gb = (const float4*)g_bsplit;          // [2][8192] float4
    int srcBase[8];
    uint32_t dstOff[8];
#pragma unroll
    for (int i = 0; i < 8; ++i) {
        int u = i * NTHREADS + tid;                      // 2 splits x 64 rows x 16 f4
        int p = u >> 10, rem = u & 1023, row = rem >> 4, c4 = rem & 15;
        srcBase[i] = p * 8192 + row * 16 + c4;
        dstOff[i]  = (uint32_t)(p * BSZ + row * RSTRIDE + c4 * 16);
    }
    float4 v[8];
#pragma unroll
    for (int i = 0; i < 8; ++i) v[i] = gb[srcBase[i]];   // chunk 0
    __syncthreads();

    // per-thread fragment addresses
    const int mbase = (wid & 3) * 16;
    const int nhalf = wid >> 2;
    const int sel = lane >> 3, l7 = lane & 7;
    const uint32_t aAddr = sbase + OFF_A
        + (uint32_t)((mbase + (sel & 1) * 8 + l7) * RSTRIDE + (sel >> 1) * 16);
    const uint32_t bAddrG0 = sbase + OFF_B
        + (uint32_t)((nhalf * 32 + (sel >> 1) * 8 + l7) * RSTRIDE + (sel & 1) * 16);
    const uint32_t bAddrG1 = bAddrG0 + 16 * RSTRIDE;

    const int r1 = mbase + (lane >> 2), r2 = r1 + 8;
    const float rs1 = s_rowsq[r1], rs2 = s_rowsq[r2];

    // ---- GEMM over 8 n-chunks of 64 cols ----
    for (int c = 0; c < 8; ++c) {
        // store staged B regs to smem
#pragma unroll
        for (int i = 0; i < 8; ++i) *(float4*)(s_b + dstOff[i]) = v[i];
        __syncthreads();
        if (c < 7) {
#pragma unroll
            for (int i = 0; i < 8; ++i) v[i] = gb[srcBase[i] + (c + 1) * 1024];
        }

        float acc[4][4];
#pragma unroll
        for (int nt = 0; nt < 4; ++nt)
#pragma unroll
            for (int j = 0; j < 4; ++j) acc[nt][j] = 0.f;

#pragma unroll
        for (int kc = 0; kc < 8; ++kc) {
            uint32_t A0[4], A1[4], B0[8], B1[8];
            uint32_t ko = (uint32_t)(kc * 32);
            LDSM_X4(A0[0], A0[1], A0[2], A0[3], aAddr + ko);
            LDSM_X4(A1[0], A1[1], A1[2], A1[3], aAddr + ASZ + ko);
            LDSM_X4(B0[0], B0[1], B0[2], B0[3], bAddrG0 + ko);
            LDSM_X4(B0[4], B0[5], B0[6], B0[7], bAddrG1 + ko);
            LDSM_X4(B1[0], B1[1], B1[2], B1[3], bAddrG0 + BSZ + ko);
            LDSM_X4(B1[4], B1[5], B1[6], B1[7], bAddrG1 + BSZ + ko);
#pragma unroll
            for (int nt = 0; nt < 4; ++nt) {
                mma16816(acc[nt], A0, B0[nt * 2], B0[nt * 2 + 1]);   // a0*b0
                mma16816(acc[nt], A0, B1[nt * 2], B1[nt * 2 + 1]);   // a0*b1
                mma16816(acc[nt], A1, B0[nt * 2], B0[nt * 2 + 1]);   // a1*b0
            }
        }

        // dist = fl( fl(rowsq+embsq) - 2*dot ) into smem
#pragma unroll
        for (int nt = 0; nt < 4; ++nt) {
            int ng = c * 64 + nhalf * 32 + nt * 8 + (lane & 3) * 2;
            float2 es = *(const float2*)(s_esq + ng);
            float2 dA, dB;
            dA.x = __fmaf_rn(-2.f, acc[nt][0], __fadd_rn(rs1, es.x));
            dA.y = __fmaf_rn(-2.f, acc[nt][1], __fadd_rn(rs1, es.y));
            dB.x = __fmaf_rn(-2.f, acc[nt][2], __fadd_rn(rs2, es.x));
            dB.y = __fmaf_rn(-2.f, acc[nt][3], __fadd_rn(rs2, es.y));
            *(float2*)(s_dist + r1 * DSTRIDE + ng) = dA;
            *(float2*)(s_dist + r2 * DSTRIDE + ng) = dB;
        }
        __syncthreads();
    }

    // ---- epilogue: per-warp rows, approx-min -> exact rescue -> softmax -> outputs ----
    float warp_sq = 0.f, warp_cm = 0.f;

#pragma unroll 1
    for (int i = 0; i < 8; ++i) {
        int r = wid * 8 + i;
        const float* dr = s_dist + r * DSTRIDE;

        float dv[16];
        float bv = 3.4e38f;
#pragma unroll
        for (int t = 0; t < 16; ++t) {
            float x = dr[lane + 32 * t];
            dv[t] = x;
            bv = fminf(bv, x);
        }
#pragma unroll
        for (int o = 16; o; o >>= 1)
            bv = fminf(bv, __shfl_xor_sync(0xffffffffu, bv, o));

        // rescue: exact recompute of near-min candidates on the reference grid
        const float margin = fmaxf(1e-4f, fabsf(bv) * 1e-6f);
        const float rsq = s_rowsq[r];
        const float* lrow = latents + (row0 + r) * D_DIM;
        float bestd = 3.4e38f;
        int bestk = 0x7fffffff;
#pragma unroll 1
        for (int t = 0; t < 16; ++t) {
            if (dv[t] <= bv + margin) {
                int k = lane + 32 * t;
                const float* er = emb + (size_t)k * D_DIM;
                float a = 0.f;
                for (int d = 0; d < D_DIM; ++d)
                    a = __fmaf_rn(lrow[d], er[d], a);
                float de = __fmaf_rn(-2.f, a, __fadd_rn(rsq, s_esq[k]));
                if (de < bestd || (de == bestd && k < bestk)) { bestd = de; bestk = k; }
            }
        }
#pragma unroll
        for (int o = 16; o; o >>= 1) {
            float od = __shfl_xor_sync(0xffffffffu, bestd, o);
            int   ok = __shfl_xor_sync(0xffffffffu, bestk, o);
            if (od < bestd || (od == bestd && ok < bestk)) { bestd = od; bestk = ok; }
        }

        long long rg = row0 + r;
        if (lane == 0) {
            atomicAdd(&g_counts[bestk], 1u);
            out_ind[rg] = (float)bestk;
            warp_cm += bestd;
        }

        // softmax(-beta*dist), stabilized at approx min
        float ev[16], sum = 0.f;
#pragma unroll
        for (int t = 0; t < 16; ++t) {
            float e = __expf(-SOFTMIN_BETA * (dv[t] - bv));
            ev[t] = e;
            sum += e;
        }
#pragma unroll
        for (int o = 16; o; o >>= 1) sum += __shfl_xor_sync(0xffffffffu, sum, o);
        float inv = 1.0f / sum;
        float* os = out_soft + rg * K_DIM;
#pragma unroll
        for (int t = 0; t < 16; ++t) os[lane + 32 * t] = ev[t] * inv;

        // quantized + loss accumulation
        float4 qv = ((const float4*)emb)[bestk * 32 + lane];
        float4 lv = ((const float4*)(latents + rg * D_DIM))[lane];
        ((float4*)(out_q + rg * D_DIM))[lane] = qv;
        float dx = qv.x - lv.x, dy = qv.y - lv.y, dz = qv.z - lv.z, dw = qv.w - lv.w;
        float sq = dx * dx + dy * dy + dz * dz + dw * dw;
#pragma unroll
        for (int o = 16; o; o >>= 1) sq += __shfl_xor_sync(0xffffffffu, sq, o);
        if (lane == 0) warp_sq += sq;
    }

    if (lane == 0) {
        atomicAdd(&g_sq_sum, (double)warp_sq);
        atomicAdd(&g_mind_sum, (double)warp_cm);
    }
}

// ---------------- finalize: scalars ----------------
__global__ void vq_fin_kernel(float* __restrict__ out_vq,
                              float* __restrict__ out_ent,
                              float* __restrict__ out_cm,
                              long long B)
{
    __shared__ float red[K_DIM];
    int k = threadIdx.x;
    float p = (float)g_counts[k] / (float)B;
    red[k] = -p * logf(p + 1e-10f);
    __syncthreads();
    for (int s = K_DIM / 2; s > 0; s >>= 1) {
        if (k < s) red[k] += red[k + s];
        __syncthreads();
    }
    if (k == 0) {
        double bd = (double)B;
        out_vq[0]  = (float)((g_sq_sum / (bd * (double)D_DIM)) * 1.25);
        out_ent[0] = red[0];
        out_cm[0]  = (float)(g_mind_sum / bd);
    }
}

extern "C" void kernel_launch(void* const* d_in, const int* in_sizes, int n_in,
                              void* d_out, int out_size)
{
    const float* latents = (const float*)d_in[0];
    const float* emb     = (const float*)d_in[1];
    long long B = (long long)in_sizes[0] / D_DIM;

    float* out      = (float*)d_out;
    float* out_q    = out;
    float* out_vq   = out + B * D_DIM;
    float* out_ent  = out_vq + 1;
    float* out_ind  = out_ent + 1;
    float* out_soft = out_ind + B;
    float* out_cm   = out_soft + B * K_DIM;

    cudaFuncSetAttribute(vq_main_kernel, cudaFuncAttributeMaxDynamicSharedMemorySize, SMEM_BYTES);

    vq_init_kernel<<<16, 32>>>(emb);
    vq_main_kernel<<<(unsigned)(B / TMROWS), NTHREADS, SMEM_BYTES>>>(latents, emb, out_q, out_ind, out_soft);
    vq_fin_kernel<<<1, K_DIM>>>(out_vq, out_ent, out_cm, B);
}